// round 1
// baseline (speedup 1.0000x reference)
#include <cuda_runtime.h>
#include <stdint.h>

// Problem constants
#define B_BATCH 8
#define SEQ     4096
#define DIN     1024
#define DOUT    1024
#define RTOT    104

// 32 MB scratch for folded weights W_eff[b][o][d]
__device__ float g_weff[(size_t)B_BATCH * DOUT * DIN];

// ---------------------------------------------------------------------------
// Prep kernel: W_eff[b][o][d] = base_w[o][d]
//                             + (1/3) * sum_r pu_w[o][r]*(1+mem[b][r])*pd_w[r][d]
// Tile: 32 (o) x 64 (d), K = RTOT = 104 fully resident in smem. 128 threads,
// each computes 4x4 outputs.
// ---------------------------------------------------------------------------
#define PO 32
#define PD 64

__global__ __launch_bounds__(128) void prep_kernel(
    const float* __restrict__ base_w,
    const float* __restrict__ pd_w,
    const float* __restrict__ pu_w,
    const float* __restrict__ mem_f,
    const float* __restrict__ mem_m,
    const float* __restrict__ mem_s)
{
    __shared__ float pu_s[PO][RTOT];   // modulation + 1/3 folded in
    __shared__ float pd_s[RTOT][PD];

    const int b  = blockIdx.z;
    const int o0 = blockIdx.y * PO;
    const int d0 = blockIdx.x * PD;
    const int tid = threadIdx.x;

    for (int i = tid; i < PO * RTOT; i += 128) {
        int o = i / RTOT, r = i % RTOT;
        float memv;
        if (r < 8)       memv = mem_f[b * 8  + r];
        else if (r < 40) memv = mem_m[b * 32 + (r - 8)];
        else             memv = mem_s[b * 64 + (r - 40)];
        pu_s[o][r] = pu_w[(size_t)(o0 + o) * RTOT + r] * (1.0f + memv) * (1.0f / 3.0f);
    }
    for (int i = tid; i < RTOT * PD; i += 128) {
        int r = i / PD, d = i % PD;
        pd_s[r][d] = pd_w[(size_t)r * DIN + d0 + d];
    }
    __syncthreads();

    const int ty = tid >> 4;   // 0..7  -> 4 o-rows each
    const int tx = tid & 15;   // 0..15 -> 4 d-cols each (float4)

    float acc[4][4];
    #pragma unroll
    for (int i = 0; i < 4; i++)
        #pragma unroll
        for (int j = 0; j < 4; j++) acc[i][j] = 0.0f;

    #pragma unroll 4
    for (int r = 0; r < RTOT; r++) {
        float a0 = pu_s[ty * 4 + 0][r];
        float a1 = pu_s[ty * 4 + 1][r];
        float a2 = pu_s[ty * 4 + 2][r];
        float a3 = pu_s[ty * 4 + 3][r];
        float4 bv = *(const float4*)&pd_s[r][tx * 4];
        acc[0][0] += a0 * bv.x; acc[0][1] += a0 * bv.y; acc[0][2] += a0 * bv.z; acc[0][3] += a0 * bv.w;
        acc[1][0] += a1 * bv.x; acc[1][1] += a1 * bv.y; acc[1][2] += a1 * bv.z; acc[1][3] += a1 * bv.w;
        acc[2][0] += a2 * bv.x; acc[2][1] += a2 * bv.y; acc[2][2] += a2 * bv.z; acc[2][3] += a2 * bv.w;
        acc[3][0] += a3 * bv.x; acc[3][1] += a3 * bv.y; acc[3][2] += a3 * bv.z; acc[3][3] += a3 * bv.w;
    }

    #pragma unroll
    for (int i = 0; i < 4; i++) {
        int o = o0 + ty * 4 + i;
        const float4 bw = *(const float4*)(base_w + (size_t)o * DIN + d0 + tx * 4);
        float4 res;
        res.x = bw.x + acc[i][0];
        res.y = bw.y + acc[i][1];
        res.z = bw.z + acc[i][2];
        res.w = bw.w + acc[i][3];
        *(float4*)(g_weff + ((size_t)b * DOUT + o) * DIN + d0 + tx * 4) = res;
    }
}

// ---------------------------------------------------------------------------
// Main GEMM: out[b] = x[b] @ W_eff[b]^T + base_b    (per batch: 4096x1024x1024)
// tf32 mma.sync m16n8k8, CTA tile 128x128x32, 8 warps (64x32 warp tiles),
// cp.async double-buffered smem. Smem row stride 36 floats -> fragment loads
// are bank-conflict-free (bank = lr*4 + lc = lane id).
// ---------------------------------------------------------------------------
#define BM 128
#define BN 128
#define BK 32
#define KSTRIDE 36
#define NKT (DIN / BK)                    // 32 k-tiles
#define TILE_FLOATS (BM * KSTRIDE)        // 4608 floats per tile buffer
#define SMEM_FLOATS (4 * TILE_FLOATS)     // A[2] + B[2]
#define SMEM_BYTES  (SMEM_FLOATS * 4)     // 73728 B

__device__ __forceinline__ void cp_async16(uint32_t saddr, const void* gptr) {
    asm volatile("cp.async.cg.shared.global [%0], [%1], 16;\n"
                 :: "r"(saddr), "l"(gptr));
}
__device__ __forceinline__ void cp_commit() {
    asm volatile("cp.async.commit_group;\n");
}
__device__ __forceinline__ void cp_wait_all() {
    asm volatile("cp.async.wait_group 0;\n");
}
__device__ __forceinline__ uint32_t f2tf32(float f) {
    uint32_t u;
    asm("cvt.rna.tf32.f32 %0, %1;" : "=r"(u) : "f"(f));
    return u;
}
__device__ __forceinline__ void mma_tf32(float c[4],
                                         uint32_t a0, uint32_t a1, uint32_t a2, uint32_t a3,
                                         uint32_t b0, uint32_t b1) {
    asm volatile("mma.sync.aligned.m16n8k8.row.col.f32.tf32.tf32.f32 "
                 "{%0,%1,%2,%3}, {%4,%5,%6,%7}, {%8,%9}, {%0,%1,%2,%3};\n"
                 : "+f"(c[0]), "+f"(c[1]), "+f"(c[2]), "+f"(c[3])
                 : "r"(a0), "r"(a1), "r"(a2), "r"(a3), "r"(b0), "r"(b1));
}

__device__ __forceinline__ void load_tiles(uint32_t sA, uint32_t sB,
                                           const float* Ag, const float* Bg,
                                           int koff, int tid) {
    #pragma unroll
    for (int i = 0; i < 4; i++) {
        int c   = tid + i * 256;          // 1024 16B-chunks per tile
        int row = c >> 3;                 // 0..127
        int q   = c & 7;                  // 8 x 16B per 128B row
        uint32_t soff = (uint32_t)(row * KSTRIDE + q * 4) * 4u;
        cp_async16(sA + soff, Ag + (size_t)row * DIN + koff + q * 4);
        cp_async16(sB + soff, Bg + (size_t)row * DIN + koff + q * 4);
    }
}

__global__ __launch_bounds__(256) void gemm_kernel(
    const float* __restrict__ x,
    const float* __restrict__ base_b,
    float* __restrict__ out)
{
    extern __shared__ float smem[];
    float* As = smem;                     // [2][BM][KSTRIDE]
    float* Bs = smem + 2 * TILE_FLOATS;   // [2][BN][KSTRIDE]

    const int b  = blockIdx.z;
    const int mt = blockIdx.y;
    const int nt = blockIdx.x;

    const float* Ag = x      + ((size_t)b * SEQ  + (size_t)mt * BM) * DIN;
    const float* Bg = g_weff + ((size_t)b * DOUT + (size_t)nt * BN) * DIN;

    const int tid  = threadIdx.x;
    const int lane = tid & 31;
    const int wid  = tid >> 5;            // 8 warps
    const int wm   = wid >> 2;            // 0..1 -> 64-row band
    const int wn   = wid & 3;             // 0..3 -> 32-col band
    const int lr   = lane >> 2;           // 0..7
    const int lc   = lane & 3;            // 0..3

    const uint32_t sA0 = (uint32_t)__cvta_generic_to_shared(As);
    const uint32_t sB0 = (uint32_t)__cvta_generic_to_shared(Bs);

    float acc[4][4][4];
    #pragma unroll
    for (int mf = 0; mf < 4; mf++)
        #pragma unroll
        for (int nf = 0; nf < 4; nf++)
            #pragma unroll
            for (int k = 0; k < 4; k++) acc[mf][nf][k] = 0.0f;

    // prologue: stage tile 0
    load_tiles(sA0, sB0, Ag, Bg, 0, tid);
    cp_commit();

    for (int kt = 0; kt < NKT; kt++) {
        cp_wait_all();
        __syncthreads();

        if (kt + 1 < NKT) {
            int nb = (kt + 1) & 1;
            load_tiles(sA0 + (uint32_t)(nb * TILE_FLOATS) * 4u,
                       sB0 + (uint32_t)(nb * TILE_FLOATS) * 4u,
                       Ag, Bg, (kt + 1) * BK, tid);
            cp_commit();
        }

        const float* At = As + (kt & 1) * TILE_FLOATS;
        const float* Bt = Bs + (kt & 1) * TILE_FLOATS;

        #pragma unroll
        for (int ks = 0; ks < 4; ks++) {
            const int kk = ks * 8;

            uint32_t afr[4][4];
            #pragma unroll
            for (int mf = 0; mf < 4; mf++) {
                const float* p = At + (wm * 64 + mf * 16 + lr) * KSTRIDE + kk + lc;
                afr[mf][0] = f2tf32(p[0]);
                afr[mf][1] = f2tf32(p[8 * KSTRIDE]);
                afr[mf][2] = f2tf32(p[4]);
                afr[mf][3] = f2tf32(p[8 * KSTRIDE + 4]);
            }
            uint32_t bfr[4][2];
            #pragma unroll
            for (int nf = 0; nf < 4; nf++) {
                const float* p = Bt + (wn * 32 + nf * 8 + lr) * KSTRIDE + kk + lc;
                bfr[nf][0] = f2tf32(p[0]);
                bfr[nf][1] = f2tf32(p[4]);
            }
            #pragma unroll
            for (int mf = 0; mf < 4; mf++)
                #pragma unroll
                for (int nf = 0; nf < 4; nf++)
                    mma_tf32(acc[mf][nf],
                             afr[mf][0], afr[mf][1], afr[mf][2], afr[mf][3],
                             bfr[nf][0], bfr[nf][1]);
        }
    }

    // epilogue: + base_b, write fp32 output
    float* Cg = out + ((size_t)b * SEQ + (size_t)mt * BM) * DOUT + (size_t)nt * BN;
    #pragma unroll
    for (int mf = 0; mf < 4; mf++) {
        int row = wm * 64 + mf * 16 + lr;
        #pragma unroll
        for (int nf = 0; nf < 4; nf++) {
            int col = wn * 32 + nf * 8 + lc * 2;
            float bias0 = base_b[nt * BN + col];
            float bias1 = base_b[nt * BN + col + 1];
            float2 r0, r1;
            r0.x = acc[mf][nf][0] + bias0;
            r0.y = acc[mf][nf][1] + bias1;
            r1.x = acc[mf][nf][2] + bias0;
            r1.y = acc[mf][nf][3] + bias1;
            *(float2*)(Cg + (size_t)row * DOUT + col)       = r0;
            *(float2*)(Cg + (size_t)(row + 8) * DOUT + col) = r1;
        }
    }
}

// ---------------------------------------------------------------------------
// Launch
// ---------------------------------------------------------------------------
extern "C" void kernel_launch(void* const* d_in, const int* in_sizes, int n_in,
                              void* d_out, int out_size) {
    const float* x      = (const float*)d_in[0];
    const float* mem_f  = (const float*)d_in[1];
    const float* mem_m  = (const float*)d_in[2];
    const float* mem_s  = (const float*)d_in[3];
    const float* base_w = (const float*)d_in[4];
    const float* base_b = (const float*)d_in[5];
    const float* pd_w   = (const float*)d_in[6];
    const float* pu_w   = (const float*)d_in[7];
    // d_in[8..11]: gate network weights — mathematically dead
    // (softmax sums to 1, mean over 3-way axis == 1/3 exactly).
    float* out = (float*)d_out;

    prep_kernel<<<dim3(DIN / PD, DOUT / PO, B_BATCH), 128>>>(
        base_w, pd_w, pu_w, mem_f, mem_m, mem_s);

    cudaFuncSetAttribute(gemm_kernel,
                         cudaFuncAttributeMaxDynamicSharedMemorySize, SMEM_BYTES);
    gemm_kernel<<<dim3(DOUT / BN, SEQ / BM, B_BATCH), 256, SMEM_BYTES>>>(
        x, base_b, out);
}

// round 3
// speedup vs baseline: 1.6226x; 1.6226x over previous
#include <cuda_runtime.h>
#include <cuda_fp16.h>
#include <stdint.h>

// Problem constants
#define B_BATCH 8
#define SEQ     4096
#define DIN     1024
#define DOUT    1024
#define RTOT    104

// Scratch: fp16 folded weights (16 MB) and fp16 x (64 MB)
__device__ __half g_wh[(size_t)B_BATCH * DOUT * DIN];
__device__ __half g_xh[(size_t)B_BATCH * SEQ * DIN];

// ---------------------------------------------------------------------------
// x -> fp16 convert. 8*4096*1024 floats = 8.39M float4, one per thread.
// ---------------------------------------------------------------------------
__global__ __launch_bounds__(256) void conv_x_kernel(const float4* __restrict__ x4) {
    size_t i = (size_t)blockIdx.x * 256 + threadIdx.x;
    float4 v = x4[i];
    __half2* o = (__half2*)(g_xh + i * 4);
    o[0] = __floats2half2_rn(v.x, v.y);
    o[1] = __floats2half2_rn(v.z, v.w);
}

// ---------------------------------------------------------------------------
// Prep kernel: W_eff[b][o][d] = base_w[o][d]
//              + (1/3)*sum_r pu_w[o][r]*(1+mem[b][r])*pd_w[r][d],  stored fp16.
// ---------------------------------------------------------------------------
#define PO 32
#define PD 64

__global__ __launch_bounds__(128) void prep_kernel(
    const float* __restrict__ base_w,
    const float* __restrict__ pd_w,
    const float* __restrict__ pu_w,
    const float* __restrict__ mem_f,
    const float* __restrict__ mem_m,
    const float* __restrict__ mem_s)
{
    __shared__ float pu_s[PO][RTOT];
    __shared__ float pd_s[RTOT][PD];

    const int b  = blockIdx.z;
    const int o0 = blockIdx.y * PO;
    const int d0 = blockIdx.x * PD;
    const int tid = threadIdx.x;

    for (int i = tid; i < PO * RTOT; i += 128) {
        int o = i / RTOT, r = i % RTOT;
        float memv;
        if (r < 8)       memv = mem_f[b * 8  + r];
        else if (r < 40) memv = mem_m[b * 32 + (r - 8)];
        else             memv = mem_s[b * 64 + (r - 40)];
        pu_s[o][r] = pu_w[(size_t)(o0 + o) * RTOT + r] * (1.0f + memv) * (1.0f / 3.0f);
    }
    for (int i = tid; i < RTOT * PD; i += 128) {
        int r = i / PD, d = i % PD;
        pd_s[r][d] = pd_w[(size_t)r * DIN + d0 + d];
    }
    __syncthreads();

    const int ty = tid >> 4;
    const int tx = tid & 15;

    float acc[4][4];
    #pragma unroll
    for (int i = 0; i < 4; i++)
        #pragma unroll
        for (int j = 0; j < 4; j++) acc[i][j] = 0.0f;

    #pragma unroll 4
    for (int r = 0; r < RTOT; r++) {
        float a0 = pu_s[ty * 4 + 0][r];
        float a1 = pu_s[ty * 4 + 1][r];
        float a2 = pu_s[ty * 4 + 2][r];
        float a3 = pu_s[ty * 4 + 3][r];
        float4 bv = *(const float4*)&pd_s[r][tx * 4];
        acc[0][0] += a0 * bv.x; acc[0][1] += a0 * bv.y; acc[0][2] += a0 * bv.z; acc[0][3] += a0 * bv.w;
        acc[1][0] += a1 * bv.x; acc[1][1] += a1 * bv.y; acc[1][2] += a1 * bv.z; acc[1][3] += a1 * bv.w;
        acc[2][0] += a2 * bv.x; acc[2][1] += a2 * bv.y; acc[2][2] += a2 * bv.z; acc[2][3] += a2 * bv.w;
        acc[3][0] += a3 * bv.x; acc[3][1] += a3 * bv.y; acc[3][2] += a3 * bv.z; acc[3][3] += a3 * bv.w;
    }

    #pragma unroll
    for (int i = 0; i < 4; i++) {
        int o = o0 + ty * 4 + i;
        const float4 bw = *(const float4*)(base_w + (size_t)o * DIN + d0 + tx * 4);
        __half2 h01 = __floats2half2_rn(bw.x + acc[i][0], bw.y + acc[i][1]);
        __half2 h23 = __floats2half2_rn(bw.z + acc[i][2], bw.w + acc[i][3]);
        __half2* dst = (__half2*)(g_wh + ((size_t)b * DOUT + o) * DIN + d0 + tx * 4);
        dst[0] = h01;
        dst[1] = h23;
    }
}

// ---------------------------------------------------------------------------
// Main GEMM: out[b] = x[b] @ W_eff[b]^T + base_b,  fp16 mma.sync m16n8k16.
// CTA tile 128(M) x 256(N), BK=64, 8 warps (2x4), warp tile 64x64.
// 4-stage cp.async pipeline, XOR-swizzled smem (128B rows), ldmatrix.x4 feeds.
// ---------------------------------------------------------------------------
#define BM 128
#define BN 256
#define BK 64                                  // halves per stage (128 B rows)
#define NKT (DIN / BK)                         // 16
#define STAGES 4
#define A_STAGE_BYTES (BM * 128)               // 16 KB
#define B_STAGE_BYTES (BN * 128)               // 32 KB
#define STAGE_BYTES (A_STAGE_BYTES + B_STAGE_BYTES)   // 48 KB
#define SMEM_BYTES (STAGES * STAGE_BYTES + 1024)

__device__ __forceinline__ uint32_t smem_u32(const void* p) {
    return (uint32_t)__cvta_generic_to_shared(p);
}
__device__ __forceinline__ void cp_async16(uint32_t saddr, const void* gptr) {
    asm volatile("cp.async.cg.shared.global [%0], [%1], 16;\n" :: "r"(saddr), "l"(gptr));
}
__device__ __forceinline__ void cp_commit() {
    asm volatile("cp.async.commit_group;\n");
}
template <int N>
__device__ __forceinline__ void cp_wait() {
    asm volatile("cp.async.wait_group %0;\n" :: "n"(N));
}
__device__ __forceinline__ void ldmatrix_x4(uint32_t r[4], uint32_t addr) {
    asm volatile("ldmatrix.sync.aligned.m8n8.x4.shared.b16 {%0,%1,%2,%3}, [%4];"
                 : "=r"(r[0]), "=r"(r[1]), "=r"(r[2]), "=r"(r[3]) : "r"(addr));
}
__device__ __forceinline__ void mma_f16(float c[4], const uint32_t a[4],
                                        uint32_t b0, uint32_t b1) {
    asm volatile("mma.sync.aligned.m16n8k16.row.col.f32.f16.f16.f32 "
                 "{%0,%1,%2,%3}, {%4,%5,%6,%7}, {%8,%9}, {%0,%1,%2,%3};\n"
                 : "+f"(c[0]), "+f"(c[1]), "+f"(c[2]), "+f"(c[3])
                 : "r"(a[0]), "r"(a[1]), "r"(a[2]), "r"(a[3]), "r"(b0), "r"(b1));
}

__global__ __launch_bounds__(256, 1) void gemm_kernel(
    const float* __restrict__ base_b,
    float* __restrict__ out)
{
    extern __shared__ char dsmem_raw[];
    const uint32_t dyn = (smem_u32(dsmem_raw) + 1023u) & ~1023u;

    const int tid  = threadIdx.x;
    const int lane = tid & 31;
    const int wid  = tid >> 5;
    const int wm   = wid >> 2;        // 0..1: 64-row M band
    const int wn   = wid & 3;         // 0..3: 64-col N band

    const int b  = blockIdx.z;
    const int mt = blockIdx.y;
    const int nt = blockIdx.x;

    const __half* Ag = g_xh + ((size_t)b * SEQ  + (size_t)mt * BM) * DIN;
    const __half* Bg = g_wh + ((size_t)b * DOUT + (size_t)nt * BN) * DIN;

    // ldmatrix lane geometry
    const int mi    = lane >> 3;        // matrix index 0..3
    const int rl    = lane & 7;
    const int half8 = (mi & 1) << 3;    // row +8 for matrices 1,3
    const int gsel  = mi >> 1;          // k-granule +1 for matrices 2,3
    const int rA    = wm * 64 + half8 + rl;   // lane's A row (+ mf*16)
    const int rB    = wn * 64 + half8 + rl;   // lane's B row (+ nfp*16)
    const uint32_t swA = (uint32_t)(rA & 7);
    const uint32_t swB = (uint32_t)(rB & 7);

    float acc[4][8][4];
    #pragma unroll
    for (int mf = 0; mf < 4; mf++)
        #pragma unroll
        for (int nf = 0; nf < 8; nf++)
            #pragma unroll
            for (int k = 0; k < 4; k++) acc[mf][nf][k] = 0.0f;

    auto load_stage = [&](int st) {
        const uint32_t base = dyn + (uint32_t)(st & (STAGES - 1)) * STAGE_BYTES;
        const int koff = st * BK;
        // A: 128 rows x 8 chunks = 1024
        #pragma unroll
        for (int i = 0; i < 4; i++) {
            int c = tid + i * 256;
            int row = c >> 3, q = c & 7;
            uint32_t dst = base + (uint32_t)(row * 128) + (uint32_t)((q ^ (row & 7)) << 4);
            cp_async16(dst, Ag + (size_t)row * DIN + koff + q * 8);
        }
        // B: 256 rows x 8 chunks = 2048
        #pragma unroll
        for (int i = 0; i < 8; i++) {
            int c = tid + i * 256;
            int row = c >> 3, q = c & 7;
            uint32_t dst = base + A_STAGE_BYTES + (uint32_t)(row * 128)
                         + (uint32_t)((q ^ (row & 7)) << 4);
            cp_async16(dst, Bg + (size_t)row * DIN + koff + q * 8);
        }
        cp_commit();
    };

    // Prologue: stages 0..2 in flight
    load_stage(0);
    load_stage(1);
    load_stage(2);

    for (int kt = 0; kt < NKT; kt++) {
        cp_wait<STAGES - 2>();      // stage kt landed (for this thread)
        __syncthreads();            // visible to all; all warps done with stage kt-1

        if (kt + STAGES - 1 < NKT) load_stage(kt + STAGES - 1);
        else                       cp_commit();   // empty group keeps wait math uniform

        const uint32_t At = dyn + (uint32_t)(kt & (STAGES - 1)) * STAGE_BYTES;
        const uint32_t Bt = At + A_STAGE_BYTES;
        const uint32_t aBase = At + (uint32_t)(rA * 128);
        const uint32_t bBase = Bt + (uint32_t)(rB * 128);

        #pragma unroll
        for (int ks = 0; ks < 4; ks++) {
            uint32_t a[4][4], bf[4][4];
            #pragma unroll
            for (int mf = 0; mf < 4; mf++)
                ldmatrix_x4(a[mf], aBase + (uint32_t)(mf * 2048)
                                 + ((((uint32_t)(2 * ks) + gsel) ^ swA) << 4));
            #pragma unroll
            for (int nfp = 0; nfp < 4; nfp++)
                ldmatrix_x4(bf[nfp], bBase + (uint32_t)(nfp * 2048)
                                   + ((((uint32_t)(2 * ks) + gsel) ^ swB) << 4));
            // bf[nfp] = {b0(nf=2p), b0(nf=2p+1), b1(nf=2p), b1(nf=2p+1)}
            #pragma unroll
            for (int mf = 0; mf < 4; mf++)
                #pragma unroll
                for (int nfp = 0; nfp < 4; nfp++) {
                    mma_f16(acc[mf][2 * nfp + 0], a[mf], bf[nfp][0], bf[nfp][2]);
                    mma_f16(acc[mf][2 * nfp + 1], a[mf], bf[nfp][1], bf[nfp][3]);
                }
        }
    }

    // Epilogue: + base_b, fp32 output
    const int lr = lane >> 2;
    const int lc = lane & 3;
    float* Cg = out + ((size_t)b * SEQ + (size_t)mt * BM) * DOUT + (size_t)nt * BN;
    const float* bias = base_b + (size_t)nt * BN;

    #pragma unroll
    for (int mf = 0; mf < 4; mf++) {
        int row = wm * 64 + mf * 16 + lr;
        #pragma unroll
        for (int nf = 0; nf < 8; nf++) {
            int col = wn * 64 + nf * 8 + lc * 2;
            float b0 = bias[col], b1 = bias[col + 1];
            float2 r0, r1;
            r0.x = acc[mf][nf][0] + b0;
            r0.y = acc[mf][nf][1] + b1;
            r1.x = acc[mf][nf][2] + b0;
            r1.y = acc[mf][nf][3] + b1;
            *(float2*)(Cg + (size_t)row * DOUT + col)       = r0;
            *(float2*)(Cg + (size_t)(row + 8) * DOUT + col) = r1;
        }
    }
}

// ---------------------------------------------------------------------------
// Launch
// ---------------------------------------------------------------------------
extern "C" void kernel_launch(void* const* d_in, const int* in_sizes, int n_in,
                              void* d_out, int out_size) {
    const float* x      = (const float*)d_in[0];
    const float* mem_f  = (const float*)d_in[1];
    const float* mem_m  = (const float*)d_in[2];
    const float* mem_s  = (const float*)d_in[3];
    const float* base_w = (const float*)d_in[4];
    const float* base_b = (const float*)d_in[5];
    const float* pd_w   = (const float*)d_in[6];
    const float* pu_w   = (const float*)d_in[7];
    // d_in[8..11]: gate network weights — mathematically dead
    // (softmax sums to 1, mean over the 3-way axis == 1/3 exactly).
    float* out = (float*)d_out;

    conv_x_kernel<<<(B_BATCH * SEQ * DIN) / (256 * 4), 256>>>((const float4*)x);

    prep_kernel<<<dim3(DIN / PD, DOUT / PO, B_BATCH), 128>>>(
        base_w, pd_w, pu_w, mem_f, mem_m, mem_s);

    cudaFuncSetAttribute(gemm_kernel,
                         cudaFuncAttributeMaxDynamicSharedMemorySize, SMEM_BYTES);
    gemm_kernel<<<dim3(DOUT / BN, SEQ / BM, B_BATCH), 256, SMEM_BYTES>>>(
        base_b, out);
}

// round 4
// speedup vs baseline: 1.9468x; 1.1998x over previous
#include <cuda_runtime.h>
#include <cuda_fp16.h>
#include <stdint.h>

// Problem constants
#define B_BATCH 8
#define SEQ     4096
#define DIN     1024
#define DOUT    1024
#define RTOT    104

// Scratch: fp16 folded weights (16 MB) and fp16 x (64 MB)
__device__ __half g_wh[(size_t)B_BATCH * DOUT * DIN];
__device__ __half g_xh[(size_t)B_BATCH * SEQ * DIN];

__device__ __forceinline__ uint32_t smem_u32(const void* p) {
    return (uint32_t)__cvta_generic_to_shared(p);
}
__device__ __forceinline__ void cp_async16(uint32_t saddr, const void* gptr) {
    asm volatile("cp.async.cg.shared.global [%0], [%1], 16;\n" :: "r"(saddr), "l"(gptr));
}
__device__ __forceinline__ void cp_commit() {
    asm volatile("cp.async.commit_group;\n");
}
template <int N>
__device__ __forceinline__ void cp_wait() {
    asm volatile("cp.async.wait_group %0;\n" :: "n"(N));
}
__device__ __forceinline__ void ldmatrix_x4(uint32_t r[4], uint32_t addr) {
    asm volatile("ldmatrix.sync.aligned.m8n8.x4.shared.b16 {%0,%1,%2,%3}, [%4];"
                 : "=r"(r[0]), "=r"(r[1]), "=r"(r[2]), "=r"(r[3]) : "r"(addr));
}
__device__ __forceinline__ void ldmatrix_x4_trans(uint32_t r[4], uint32_t addr) {
    asm volatile("ldmatrix.sync.aligned.m8n8.x4.trans.shared.b16 {%0,%1,%2,%3}, [%4];"
                 : "=r"(r[0]), "=r"(r[1]), "=r"(r[2]), "=r"(r[3]) : "r"(addr));
}
__device__ __forceinline__ void mma_f16(float c[4], const uint32_t a[4],
                                        uint32_t b0, uint32_t b1) {
    asm volatile("mma.sync.aligned.m16n8k16.row.col.f32.f16.f16.f32 "
                 "{%0,%1,%2,%3}, {%4,%5,%6,%7}, {%8,%9}, {%0,%1,%2,%3};\n"
                 : "+f"(c[0]), "+f"(c[1]), "+f"(c[2]), "+f"(c[3])
                 : "r"(a[0]), "r"(a[1]), "r"(a[2]), "r"(a[3]), "r"(b0), "r"(b1));
}

// ---------------------------------------------------------------------------
// x -> fp16 convert. 8*4096*1024 floats = 8.39M float4, one per thread.
// ---------------------------------------------------------------------------
__global__ __launch_bounds__(256) void conv_x_kernel(const float4* __restrict__ x4) {
    size_t i = (size_t)blockIdx.x * 256 + threadIdx.x;
    float4 v = x4[i];
    __half2* o = (__half2*)(g_xh + i * 4);
    o[0] = __floats2half2_rn(v.x, v.y);
    o[1] = __floats2half2_rn(v.z, v.w);
}

// ---------------------------------------------------------------------------
// Tensor-core prep: W_eff[b] = base_w + pu_mod[b] @ pd  -> g_wh (fp16).
// CTA tile 128(o) x 128(d), K = 104 padded to 112, fully smem-resident.
// A = pu*(1+mem)/3 fp16 [o][r], stride 120 halves (conflict-free ldmatrix).
// B = pd fp16 [r][d], stride 136 halves; B-fragments via ldmatrix.x4.trans.
// ---------------------------------------------------------------------------
#define KP 112
#define PSA 120        // A smem stride (halves)
#define PSB 136        // B smem stride (halves)
#define PREP_A_HALVES (128 * PSA)                 // 15360
#define PREP_SMEM_BYTES ((128 * PSA + KP * PSB) * 2)  // 30720 + 30464 = 61184

__global__ __launch_bounds__(256) void prep_mma_kernel(
    const float* __restrict__ base_w,
    const float* __restrict__ pd_w,
    const float* __restrict__ pu_w,
    const float* __restrict__ mem_f,
    const float* __restrict__ mem_m,
    const float* __restrict__ mem_s)
{
    extern __shared__ __half psm[];
    __half* As = psm;                  // [128][PSA]
    __half* Bs = psm + PREP_A_HALVES;  // [KP][PSB]
    __shared__ float s_fac[KP];

    const int b  = blockIdx.z;
    const int o0 = blockIdx.y * 128;
    const int d0 = blockIdx.x * 128;
    const int tid = threadIdx.x;

    if (tid < KP) {
        float f = 0.0f;
        int r = tid;
        if (r < RTOT) {
            float memv;
            if (r < 8)       memv = mem_f[b * 8  + r];
            else if (r < 40) memv = mem_m[b * 32 + (r - 8)];
            else             memv = mem_s[b * 64 + (r - 40)];
            f = (1.0f + memv) * (1.0f / 3.0f);
        }
        s_fac[r] = f;
    }
    __syncthreads();

    // A fill: 128 x 112 (r >= RTOT zero)
    for (int i = tid; i < 128 * KP; i += 256) {
        int o = i / KP, r = i - o * KP;
        float v = (r < RTOT) ? pu_w[(size_t)(o0 + o) * RTOT + r] * s_fac[r] : 0.0f;
        As[o * PSA + r] = __float2half(v);
    }
    // B fill: 112 x 128 (rows >= RTOT zero)
    for (int i = tid; i < KP * 128; i += 256) {
        int r = i >> 7, d = i & 127;
        float v = (r < RTOT) ? pd_w[(size_t)r * DIN + d0 + d] : 0.0f;
        Bs[r * PSB + d] = __float2half(v);
    }
    __syncthreads();

    const int lane = tid & 31;
    const int wid  = tid >> 5;
    const int wm   = wid >> 2;         // 0..1: 64 o-rows
    const int wn   = wid & 3;          // 0..3: 32 d-cols

    const int mi = lane >> 3;
    const int rl = lane & 7;
    const int aRow = wm * 64 + ((mi & 1) << 3) + rl;   // + mf*16
    const int gsel = mi >> 1;                          // k-granule for A
    const int bK   = ((mi >> 1) << 3) + rl;            // + ks*16
    const int bN   = wn * 32 + ((mi & 1) << 3);        // + nfp*16

    const uint32_t sA = smem_u32(As);
    const uint32_t sB = smem_u32(Bs);

    float acc[4][4][4];
    #pragma unroll
    for (int mf = 0; mf < 4; mf++)
        #pragma unroll
        for (int nf = 0; nf < 4; nf++)
            #pragma unroll
            for (int k = 0; k < 4; k++) acc[mf][nf][k] = 0.0f;

    #pragma unroll
    for (int ks = 0; ks < KP / 16; ks++) {
        uint32_t a[4][4], bf[2][4];
        #pragma unroll
        for (int mf = 0; mf < 4; mf++)
            ldmatrix_x4(a[mf],
                sA + (uint32_t)(((aRow + mf * 16) * PSA + ks * 16 + gsel * 8) * 2));
        #pragma unroll
        for (int nfp = 0; nfp < 2; nfp++)
            ldmatrix_x4_trans(bf[nfp],
                sB + (uint32_t)(((ks * 16 + bK) * PSB + bN + nfp * 16) * 2));
        #pragma unroll
        for (int mf = 0; mf < 4; mf++)
            #pragma unroll
            for (int nfp = 0; nfp < 2; nfp++) {
                mma_f16(acc[mf][2 * nfp + 0], a[mf], bf[nfp][0], bf[nfp][2]);
                mma_f16(acc[mf][2 * nfp + 1], a[mf], bf[nfp][1], bf[nfp][3]);
            }
    }

    // Epilogue: + base_w, write fp16 W_eff
    const int lr = lane >> 2;
    const int lc = lane & 3;
    #pragma unroll
    for (int mf = 0; mf < 4; mf++) {
        int row = o0 + wm * 64 + mf * 16 + lr;
        #pragma unroll
        for (int nf = 0; nf < 4; nf++) {
            int col = d0 + wn * 32 + nf * 8 + lc * 2;
            const float* bwp0 = base_w + (size_t)row * DIN + col;
            const float* bwp1 = base_w + (size_t)(row + 8) * DIN + col;
            __half2 h0 = __floats2half2_rn(acc[mf][nf][0] + bwp0[0],
                                           acc[mf][nf][1] + bwp0[1]);
            __half2 h1 = __floats2half2_rn(acc[mf][nf][2] + bwp1[0],
                                           acc[mf][nf][3] + bwp1[1]);
            *(__half2*)(g_wh + ((size_t)b * DOUT + row) * DIN + col)     = h0;
            *(__half2*)(g_wh + ((size_t)b * DOUT + row + 8) * DIN + col) = h1;
        }
    }
}

// ---------------------------------------------------------------------------
// Main GEMM (unchanged from round 3): out[b] = x[b] @ W_eff[b]^T + base_b.
// fp16 mma.sync m16n8k16, CTA 128x256, BK=64, 4-stage cp.async, ldmatrix.x4.
// ---------------------------------------------------------------------------
#define BM 128
#define BN 256
#define BK 64
#define NKT (DIN / BK)
#define STAGES 4
#define A_STAGE_BYTES (BM * 128)
#define B_STAGE_BYTES (BN * 128)
#define STAGE_BYTES (A_STAGE_BYTES + B_STAGE_BYTES)
#define SMEM_BYTES (STAGES * STAGE_BYTES + 1024)

__global__ __launch_bounds__(256, 1) void gemm_kernel(
    const float* __restrict__ base_b,
    float* __restrict__ out)
{
    extern __shared__ char dsmem_raw[];
    const uint32_t dyn = (smem_u32(dsmem_raw) + 1023u) & ~1023u;

    const int tid  = threadIdx.x;
    const int lane = tid & 31;
    const int wid  = tid >> 5;
    const int wm   = wid >> 2;
    const int wn   = wid & 3;

    const int b  = blockIdx.z;
    const int mt = blockIdx.y;
    const int nt = blockIdx.x;

    const __half* Ag = g_xh + ((size_t)b * SEQ  + (size_t)mt * BM) * DIN;
    const __half* Bg = g_wh + ((size_t)b * DOUT + (size_t)nt * BN) * DIN;

    const int mi    = lane >> 3;
    const int rl    = lane & 7;
    const int half8 = (mi & 1) << 3;
    const int gsel  = mi >> 1;
    const int rA    = wm * 64 + half8 + rl;
    const int rB    = wn * 64 + half8 + rl;
    const uint32_t swA = (uint32_t)(rA & 7);
    const uint32_t swB = (uint32_t)(rB & 7);

    float acc[4][8][4];
    #pragma unroll
    for (int mf = 0; mf < 4; mf++)
        #pragma unroll
        for (int nf = 0; nf < 8; nf++)
            #pragma unroll
            for (int k = 0; k < 4; k++) acc[mf][nf][k] = 0.0f;

    auto load_stage = [&](int st) {
        const uint32_t base = dyn + (uint32_t)(st & (STAGES - 1)) * STAGE_BYTES;
        const int koff = st * BK;
        #pragma unroll
        for (int i = 0; i < 4; i++) {
            int c = tid + i * 256;
            int row = c >> 3, q = c & 7;
            uint32_t dst = base + (uint32_t)(row * 128) + (uint32_t)((q ^ (row & 7)) << 4);
            cp_async16(dst, Ag + (size_t)row * DIN + koff + q * 8);
        }
        #pragma unroll
        for (int i = 0; i < 8; i++) {
            int c = tid + i * 256;
            int row = c >> 3, q = c & 7;
            uint32_t dst = base + A_STAGE_BYTES + (uint32_t)(row * 128)
                         + (uint32_t)((q ^ (row & 7)) << 4);
            cp_async16(dst, Bg + (size_t)row * DIN + koff + q * 8);
        }
        cp_commit();
    };

    load_stage(0);
    load_stage(1);
    load_stage(2);

    for (int kt = 0; kt < NKT; kt++) {
        cp_wait<STAGES - 2>();
        __syncthreads();

        if (kt + STAGES - 1 < NKT) load_stage(kt + STAGES - 1);
        else                       cp_commit();

        const uint32_t At = dyn + (uint32_t)(kt & (STAGES - 1)) * STAGE_BYTES;
        const uint32_t Bt = At + A_STAGE_BYTES;
        const uint32_t aBase = At + (uint32_t)(rA * 128);
        const uint32_t bBase = Bt + (uint32_t)(rB * 128);

        #pragma unroll
        for (int ks = 0; ks < 4; ks++) {
            uint32_t a[4][4], bf[4][4];
            #pragma unroll
            for (int mf = 0; mf < 4; mf++)
                ldmatrix_x4(a[mf], aBase + (uint32_t)(mf * 2048)
                                 + ((((uint32_t)(2 * ks) + gsel) ^ swA) << 4));
            #pragma unroll
            for (int nfp = 0; nfp < 4; nfp++)
                ldmatrix_x4(bf[nfp], bBase + (uint32_t)(nfp * 2048)
                                   + ((((uint32_t)(2 * ks) + gsel) ^ swB) << 4));
            #pragma unroll
            for (int mf = 0; mf < 4; mf++)
                #pragma unroll
                for (int nfp = 0; nfp < 4; nfp++) {
                    mma_f16(acc[mf][2 * nfp + 0], a[mf], bf[nfp][0], bf[nfp][2]);
                    mma_f16(acc[mf][2 * nfp + 1], a[mf], bf[nfp][1], bf[nfp][3]);
                }
        }
    }

    const int lr = lane >> 2;
    const int lc = lane & 3;
    float* Cg = out + ((size_t)b * SEQ + (size_t)mt * BM) * DOUT + (size_t)nt * BN;
    const float* bias = base_b + (size_t)nt * BN;

    #pragma unroll
    for (int mf = 0; mf < 4; mf++) {
        int row = wm * 64 + mf * 16 + lr;
        #pragma unroll
        for (int nf = 0; nf < 8; nf++) {
            int col = wn * 64 + nf * 8 + lc * 2;
            float b0 = bias[col], b1 = bias[col + 1];
            float2 r0, r1;
            r0.x = acc[mf][nf][0] + b0;
            r0.y = acc[mf][nf][1] + b1;
            r1.x = acc[mf][nf][2] + b0;
            r1.y = acc[mf][nf][3] + b1;
            *(float2*)(Cg + (size_t)row * DOUT + col)       = r0;
            *(float2*)(Cg + (size_t)(row + 8) * DOUT + col) = r1;
        }
    }
}

// ---------------------------------------------------------------------------
// Launch
// ---------------------------------------------------------------------------
extern "C" void kernel_launch(void* const* d_in, const int* in_sizes, int n_in,
                              void* d_out, int out_size) {
    const float* x      = (const float*)d_in[0];
    const float* mem_f  = (const float*)d_in[1];
    const float* mem_m  = (const float*)d_in[2];
    const float* mem_s  = (const float*)d_in[3];
    const float* base_w = (const float*)d_in[4];
    const float* base_b = (const float*)d_in[5];
    const float* pd_w   = (const float*)d_in[6];
    const float* pu_w   = (const float*)d_in[7];
    // d_in[8..11]: gate network weights — mathematically dead
    // (softmax sums to 1, mean over the 3-way axis == 1/3 exactly).
    float* out = (float*)d_out;

    conv_x_kernel<<<(B_BATCH * SEQ * DIN) / (256 * 4), 256>>>((const float4*)x);

    cudaFuncSetAttribute(prep_mma_kernel,
                         cudaFuncAttributeMaxDynamicSharedMemorySize, PREP_SMEM_BYTES);
    prep_mma_kernel<<<dim3(DIN / 128, DOUT / 128, B_BATCH), 256, PREP_SMEM_BYTES>>>(
        base_w, pd_w, pu_w, mem_f, mem_m, mem_s);

    cudaFuncSetAttribute(gemm_kernel,
                         cudaFuncAttributeMaxDynamicSharedMemorySize, SMEM_BYTES);
    gemm_kernel<<<dim3(DOUT / BN, SEQ / BM, B_BATCH), 256, SMEM_BYTES>>>(
        base_b, out);
}